// round 1
// baseline (speedup 1.0000x reference)
#include <cuda_runtime.h>
#include <cstdint>

// IDWT_2D: x [B=4, 4*C=256, H=256, W=256] f32, filters [4,2,2] f32
// s[b,g,h,w] = sum_n x[b, n*64+g, h, w]
// y[b, g*4+j, 2h+a, 2w+c] = s[b,g,h,w] * f[j,a,c]
// Output: [4, 256, 512, 512] f32

static constexpr int B = 4;
static constexpr int C = 64;    // groups
static constexpr int H = 256;
static constexpr int W = 256;
static constexpr int W4 = W / 4;           // float4 columns per row = 64
static constexpr int IN_CH_STRIDE = H * W; // 65536
static constexpr int OUT_W = 2 * W;        // 512
static constexpr int OUT_CH_STRIDE = (2 * H) * OUT_W; // 512*512

__global__ __launch_bounds__(256) void idwt2d_kernel(
    const float* __restrict__ x,
    const float* __restrict__ filters,
    float* __restrict__ out)
{
    // one thread = one (b, g, h, 4-wide w vector)
    unsigned t = blockIdx.x * 256u + threadIdx.x;
    int wv = t & (W4 - 1);          // 0..63
    int h  = (t >> 6) & (H - 1);    // 0..255
    int g  = (t >> 14) & (C - 1);   // 0..63
    int b  = t >> 20;               // 0..3

    // ---- gather + sum the 4 wavelet sub-band input channels ----
    // input channel for sub-band n, group g: n*C + g
    const float4* xin = reinterpret_cast<const float4*>(
        x + (((size_t)(b * 4 * C + g) * H + h) * W)) + wv;
    float4 v0 = __ldg(xin + 0 * (C * IN_CH_STRIDE / 4));
    float4 v1 = __ldg(xin + 1 * (C * IN_CH_STRIDE / 4));
    float4 v2 = __ldg(xin + 2 * (C * IN_CH_STRIDE / 4));
    float4 v3 = __ldg(xin + 3 * (C * IN_CH_STRIDE / 4));
    float4 s;
    s.x = (v0.x + v1.x) + (v2.x + v3.x);
    s.y = (v0.y + v1.y) + (v2.y + v3.y);
    s.z = (v0.z + v1.z) + (v2.z + v3.z);
    s.w = (v0.w + v1.w) + (v2.w + v3.w);

    // ---- filters: [4,2,2], one float4 per j: {a0c0, a0c1, a1c0, a1c1} ----
    const float4* f4 = reinterpret_cast<const float4*>(filters);

    // output base for (b, g, j=0, row 2h, col 2*wv*4)
    float* obase = out + ((size_t)(b * 4 * C + g * 4) * (2 * H) + 2 * h) * OUT_W
                       + 8 * wv;

    #pragma unroll
    for (int j = 0; j < 4; ++j) {
        float4 F = __ldg(f4 + j);
        float* orow = obase + (size_t)j * OUT_CH_STRIDE;
        // a = 0 row
        float4 lo, hi;
        lo.x = s.x * F.x; lo.y = s.x * F.y; lo.z = s.y * F.x; lo.w = s.y * F.y;
        hi.x = s.z * F.x; hi.y = s.z * F.y; hi.z = s.w * F.x; hi.w = s.w * F.y;
        reinterpret_cast<float4*>(orow)[0] = lo;
        reinterpret_cast<float4*>(orow)[1] = hi;
        // a = 1 row
        lo.x = s.x * F.z; lo.y = s.x * F.w; lo.z = s.y * F.z; lo.w = s.y * F.w;
        hi.x = s.z * F.z; hi.y = s.z * F.w; hi.z = s.w * F.z; hi.w = s.w * F.w;
        reinterpret_cast<float4*>(orow + OUT_W)[0] = lo;
        reinterpret_cast<float4*>(orow + OUT_W)[1] = hi;
    }
}

extern "C" void kernel_launch(void* const* d_in, const int* in_sizes, int n_in,
                              void* d_out, int out_size) {
    const float* x       = (const float*)d_in[0];
    const float* filters = (const float*)d_in[1];
    float* out           = (float*)d_out;

    // total threads = B * C * H * W4 = 4*64*256*64 = 4,194,304
    const int total = B * C * H * W4;
    idwt2d_kernel<<<total / 256, 256>>>(x, filters, out);
}